// round 2
// baseline (speedup 1.0000x reference)
#include <cuda_runtime.h>
#include <math.h>

#define N_NODES 50000
#define N_EDGES 800000
#define DD 128
#define TIME_DIM 32
#define EDGE_DIM 160
#define XDIM 256
#define EPS_F 0.1f
#define GAMMA_F 0.1f

// ---------------- static scratch (allocation-free rule) ----------------
__device__ float g_ea[(size_t)N_EDGES * EDGE_DIM];   // sorted edge_attr [E,160]
__device__ float g_e [(size_t)N_EDGES * DD];         // sorted e = ea@WeT+be [E,128]
__device__ float g_q  [(size_t)N_NODES * DD];
__device__ float g_k  [(size_t)N_NODES * DD];
__device__ float g_v  [(size_t)N_NODES * DD];
__device__ float g_phi[(size_t)N_NODES * DD];
__device__ float g_tmp[(size_t)N_NODES * DD];
__device__ float g_encWT[XDIM * DD];
__device__ float g_WeT[EDGE_DIM * DD];
__device__ float g_WqT[DD * DD];
__device__ float g_WkT[DD * DD];
__device__ float g_WvT[DD * DD];
__device__ float g_AT [DD * DD];
__device__ int   g_cnt[N_NODES];
__device__ int   g_indptr[N_NODES + 1];
__device__ int   g_cursor[N_NODES];
__device__ int   g_perm[N_EDGES];
__device__ int   g_src [N_EDGES];

// ---------------- small prep kernels ----------------
__global__ void transpose_kernel(const float* __restrict__ in, float* __restrict__ out,
                                 int R, int C) {
    int i = blockIdx.x * blockDim.x + threadIdx.x;
    if (i < R * C) {
        int r = i / C, c = i % C;
        out[c * R + r] = in[i];
    }
}

// AT[j*D + i] = A[i][j],  A = W - W^T - gamma*I
__global__ void build_AT_kernel(const float* __restrict__ W, float* __restrict__ AT) {
    int i = blockIdx.x * blockDim.x + threadIdx.x;
    if (i < DD * DD) {
        int jj = i / DD, ii = i % DD;
        float val = W[ii * DD + jj] - W[jj * DD + ii] - ((ii == jj) ? GAMMA_F : 0.0f);
        AT[jj * DD + ii] = val;
    }
}

__global__ void zero_int_kernel(int* __restrict__ p, int n) {
    int i = blockIdx.x * blockDim.x + threadIdx.x;
    if (i < n) p[i] = 0;
}

__global__ void count_dst_kernel(const int* __restrict__ ei, int* __restrict__ cnt) {
    int e = blockIdx.x * blockDim.x + threadIdx.x;
    if (e < N_EDGES) atomicAdd(&cnt[ei[N_EDGES + e]], 1);
}

__global__ void scan_kernel(const int* __restrict__ cnt, int* __restrict__ indptr,
                            int* __restrict__ cursor) {
    __shared__ int sm[1024];
    __shared__ int carry;
    if (threadIdx.x == 0) carry = 0;
    __syncthreads();
    for (int base = 0; base < N_NODES; base += 1024) {
        int i = base + threadIdx.x;
        int val = (i < N_NODES) ? cnt[i] : 0;
        sm[threadIdx.x] = val;
        __syncthreads();
        for (int off = 1; off < 1024; off <<= 1) {
            int add = 0;
            if (threadIdx.x >= off) add = sm[threadIdx.x - off];
            __syncthreads();
            sm[threadIdx.x] += add;
            __syncthreads();
        }
        if (i < N_NODES) {
            int excl = carry + sm[threadIdx.x] - val;
            indptr[i] = excl;
            cursor[i] = excl;
        }
        __syncthreads();
        if (threadIdx.x == 0) carry += sm[1023];
        __syncthreads();
    }
    if (threadIdx.x == 0) indptr[N_NODES] = carry;
}

__global__ void scatter_perm_kernel(const int* __restrict__ ei,
                                    int* __restrict__ cursor, int* __restrict__ perm) {
    int e = blockIdx.x * blockDim.x + threadIdx.x;
    if (e < N_EDGES) {
        int d = ei[N_EDGES + e];
        int pos = atomicAdd(&cursor[d], 1);
        perm[pos] = e;
    }
}

// Build sorted edge_attr [E,160] = [msg | cos(rel_t*te_w + te_b)], plus sorted src ids.
// Warp per edge, grid-stride.
__global__ void build_ea_kernel(const int* __restrict__ ei,
                                const float* __restrict__ last_update,
                                const float* __restrict__ t,
                                const float* __restrict__ msg,
                                const float* __restrict__ te_w,
                                const float* __restrict__ te_b,
                                const int* __restrict__ perm,
                                float* __restrict__ ea, int* __restrict__ srcs) {
    int warp = (blockIdx.x * blockDim.x + threadIdx.x) >> 5;
    int lane = threadIdx.x & 31;
    int nwarps = (gridDim.x * blockDim.x) >> 5;
    for (int i = warp; i < N_EDGES; i += nwarps) {
        int eid = perm[i];
        int src = ei[eid];
        float rel = fabsf(last_update[src] - t[eid]);
        if (lane == 0) srcs[i] = src;
        const float* mrow = msg + (size_t)eid * DD;
        float* orow = ea + (size_t)i * EDGE_DIM;
#pragma unroll
        for (int j = 0; j < 4; j++) orow[lane + 32 * j] = mrow[lane + 32 * j];
        orow[lane + 128] = cosf(rel * te_w[lane] + te_b[lane]);
    }
}

// ---------------- SGEMM: C[M,128] = A[M,K] @ B[K,128] + bias ----------------
// 128x128 block tile, 256 threads, 8x8 microtile, K % 16 == 0.
__global__ void sgemm128_kernel(const float* __restrict__ A, const float* __restrict__ B,
                                const float* __restrict__ bias, float* __restrict__ C,
                                int M, int K) {
    __shared__ float As[16][128];
    __shared__ float Bs[16][128];
    int tid = threadIdx.x;
    int tx = tid & 15;   // col group
    int ty = tid >> 4;   // row group
    int row0 = blockIdx.x * 128;
    float acc[8][8];
#pragma unroll
    for (int i = 0; i < 8; i++)
#pragma unroll
        for (int j = 0; j < 8; j++) acc[i][j] = 0.0f;

    for (int k0 = 0; k0 < K; k0 += 16) {
        // load A tile (transposed into smem As[kk][m])
#pragma unroll
        for (int j = 0; j < 2; j++) {
            int idx = tid + j * 256;     // 0..511 float4 slots
            int r = idx >> 2;            // 0..127
            int kq = idx & 3;            // k-offset/4
            float4 val = make_float4(0.f, 0.f, 0.f, 0.f);
            int gr = row0 + r;
            if (gr < M) val = *(const float4*)(A + (size_t)gr * K + k0 + kq * 4);
            As[kq * 4 + 0][r] = val.x;
            As[kq * 4 + 1][r] = val.y;
            As[kq * 4 + 2][r] = val.z;
            As[kq * 4 + 3][r] = val.w;
        }
        // load B tile
#pragma unroll
        for (int j = 0; j < 2; j++) {
            int idx = tid + j * 256;
            int kk = idx >> 5;           // 0..15
            int nq = idx & 31;           // col/4
            float4 val = *(const float4*)(B + (size_t)(k0 + kk) * 128 + nq * 4);
            *(float4*)(&Bs[kk][nq * 4]) = val;
        }
        __syncthreads();
#pragma unroll
        for (int kk = 0; kk < 16; kk++) {
            float a[8], b[8];
            *(float4*)(a)     = *(const float4*)(&As[kk][ty * 8]);
            *(float4*)(a + 4) = *(const float4*)(&As[kk][ty * 8 + 4]);
            *(float4*)(b)     = *(const float4*)(&Bs[kk][tx * 8]);
            *(float4*)(b + 4) = *(const float4*)(&Bs[kk][tx * 8 + 4]);
#pragma unroll
            for (int i = 0; i < 8; i++)
#pragma unroll
                for (int j = 0; j < 8; j++) acc[i][j] += a[i] * b[j];
        }
        __syncthreads();
    }
    // epilogue
#pragma unroll
    for (int i = 0; i < 8; i++) {
        int gr = row0 + ty * 8 + i;
        if (gr < M) {
#pragma unroll
            for (int jq = 0; jq < 2; jq++) {
                int c = tx * 8 + jq * 4;
                float4 o;
                o.x = acc[i][jq * 4 + 0] + bias[c + 0];
                o.y = acc[i][jq * 4 + 1] + bias[c + 1];
                o.z = acc[i][jq * 4 + 2] + bias[c + 2];
                o.w = acc[i][jq * 4 + 3] + bias[c + 3];
                *(float4*)(C + (size_t)gr * 128 + c) = o;
            }
        }
    }
}

// ---------------- attention: warp-per-dst online softmax ----------------
__global__ void attn_kernel(const float* __restrict__ q, const float* __restrict__ k,
                            const float* __restrict__ v, const float* __restrict__ e,
                            const int* __restrict__ indptr, const int* __restrict__ srcs,
                            float* __restrict__ phi) {
    int node = (blockIdx.x * blockDim.x + threadIdx.x) >> 5;
    int lane = threadIdx.x & 31;
    if (node >= N_NODES) return;
    int beg = indptr[node];
    int end = indptr[node + 1];
    float4 q4 = *(const float4*)(q + (size_t)node * DD + lane * 4);
    float4 acc = make_float4(0.f, 0.f, 0.f, 0.f);
    float m = -3.0e38f, s = 0.0f;
    const float inv_sqrt_d = 0.08838834764831845f;  // 1/sqrt(128)
    for (int i = beg; i < end; i++) {
        int src = srcs[i];
        float4 e4 = *(const float4*)(e + (size_t)i * DD + lane * 4);
        float4 k4 = *(const float4*)(k + (size_t)src * DD + lane * 4);
        float dot = q4.x * (k4.x + e4.x) + q4.y * (k4.y + e4.y)
                  + q4.z * (k4.z + e4.z) + q4.w * (k4.w + e4.w);
#pragma unroll
        for (int off = 16; off; off >>= 1) dot += __shfl_xor_sync(0xffffffffu, dot, off);
        float l = dot * inv_sqrt_d;
        float mn = fmaxf(m, l);
        float scale = __expf(m - mn);
        float w = __expf(l - mn);
        s = s * scale + w;
        float4 v4 = *(const float4*)(v + (size_t)src * DD + lane * 4);
        acc.x = acc.x * scale + (v4.x + e4.x) * w;
        acc.y = acc.y * scale + (v4.y + e4.y) * w;
        acc.z = acc.z * scale + (v4.z + e4.z) * w;
        acc.w = acc.w * scale + (v4.w + e4.w) * w;
        m = mn;
    }
    float invs = (end > beg) ? (1.0f / s) : 0.0f;
    float4 o = make_float4(acc.x * invs, acc.y * invs, acc.z * invs, acc.w * invs);
    *(float4*)(phi + (size_t)node * DD + lane * 4) = o;
}

// h += eps * tanh(tmp + phi)    (tmp already contains h@A^T + b_anti)
__global__ void update_kernel(float* __restrict__ h, const float* __restrict__ tmp,
                              const float* __restrict__ phi) {
    int i = blockIdx.x * blockDim.x + threadIdx.x;
    if (i < N_NODES * DD) h[i] += EPS_F * tanhf(tmp[i] + phi[i]);
}

// ---------------- launch ----------------
extern "C" void kernel_launch(void* const* d_in, const int* in_sizes, int n_in,
                              void* d_out, int out_size) {
    const float* x     = (const float*)d_in[0];
    const float* lastu = (const float*)d_in[1];
    const float* t     = (const float*)d_in[2];
    const float* msg   = (const float*)d_in[3];
    const int*   ei    = (const int*)d_in[4];   // JAX default: int64 silently -> int32
    const float* enc_W = (const float*)d_in[5];
    const float* enc_b = (const float*)d_in[6];
    const float* te_w  = (const float*)d_in[7];
    const float* te_b  = (const float*)d_in[8];
    const float* Wq = (const float*)d_in[9];   const float* bq = (const float*)d_in[10];
    const float* Wk = (const float*)d_in[11];  const float* bk = (const float*)d_in[12];
    const float* Wv = (const float*)d_in[13];  const float* bv = (const float*)d_in[14];
    const float* We = (const float*)d_in[15];  const float* be = (const float*)d_in[16];
    const float* W_anti = (const float*)d_in[17];
    const float* b_anti = (const float*)d_in[18];
    float* h = (float*)d_out;

    // resolve scratch symbol addresses
    float *p_ea, *p_e, *p_q, *p_k, *p_v, *p_phi, *p_tmp;
    float *p_encWT, *p_WeT, *p_WqT, *p_WkT, *p_WvT, *p_AT;
    int *p_cnt, *p_indptr, *p_cursor, *p_perm, *p_src;
    cudaGetSymbolAddress((void**)&p_ea, g_ea);
    cudaGetSymbolAddress((void**)&p_e, g_e);
    cudaGetSymbolAddress((void**)&p_q, g_q);
    cudaGetSymbolAddress((void**)&p_k, g_k);
    cudaGetSymbolAddress((void**)&p_v, g_v);
    cudaGetSymbolAddress((void**)&p_phi, g_phi);
    cudaGetSymbolAddress((void**)&p_tmp, g_tmp);
    cudaGetSymbolAddress((void**)&p_encWT, g_encWT);
    cudaGetSymbolAddress((void**)&p_WeT, g_WeT);
    cudaGetSymbolAddress((void**)&p_WqT, g_WqT);
    cudaGetSymbolAddress((void**)&p_WkT, g_WkT);
    cudaGetSymbolAddress((void**)&p_WvT, g_WvT);
    cudaGetSymbolAddress((void**)&p_AT, g_AT);
    cudaGetSymbolAddress((void**)&p_cnt, g_cnt);
    cudaGetSymbolAddress((void**)&p_indptr, g_indptr);
    cudaGetSymbolAddress((void**)&p_cursor, g_cursor);
    cudaGetSymbolAddress((void**)&p_perm, g_perm);
    cudaGetSymbolAddress((void**)&p_src, g_src);

    // --- weight prep ---
    transpose_kernel<<<(XDIM * DD + 255) / 256, 256>>>(enc_W, p_encWT, DD, XDIM);
    transpose_kernel<<<(EDGE_DIM * DD + 255) / 256, 256>>>(We, p_WeT, DD, EDGE_DIM);
    transpose_kernel<<<(DD * DD + 255) / 256, 256>>>(Wq, p_WqT, DD, DD);
    transpose_kernel<<<(DD * DD + 255) / 256, 256>>>(Wk, p_WkT, DD, DD);
    transpose_kernel<<<(DD * DD + 255) / 256, 256>>>(Wv, p_WvT, DD, DD);
    build_AT_kernel<<<(DD * DD + 255) / 256, 256>>>(W_anti, p_AT);

    // --- CSR by dst ---
    zero_int_kernel<<<(N_NODES + 255) / 256, 256>>>(p_cnt, N_NODES);
    count_dst_kernel<<<(N_EDGES + 255) / 256, 256>>>(ei, p_cnt);
    scan_kernel<<<1, 1024>>>(p_cnt, p_indptr, p_cursor);
    scatter_perm_kernel<<<(N_EDGES + 255) / 256, 256>>>(ei, p_cursor, p_perm);

    // --- sorted edge_attr + e GEMM ---
    build_ea_kernel<<<1024, 256>>>(ei, lastu, t, msg, te_w, te_b, p_perm, p_ea, p_src);
    sgemm128_kernel<<<(N_EDGES + 127) / 128, 256>>>(p_ea, p_WeT, be, p_e, N_EDGES, EDGE_DIM);

    // --- h = x @ enc_W^T + enc_b ---
    sgemm128_kernel<<<(N_NODES + 127) / 128, 256>>>(x, p_encWT, enc_b, h, N_NODES, XDIM);

    // --- 3 iterations ---
    int gemm_grid = (N_NODES + 127) / 128;
    int attn_grid = (N_NODES * 32 + 255) / 256;
    int upd_grid = (N_NODES * DD + 255) / 256;
    for (int it = 0; it < 3; it++) {
        sgemm128_kernel<<<gemm_grid, 256>>>(h, p_WqT, bq, p_q, N_NODES, DD);
        sgemm128_kernel<<<gemm_grid, 256>>>(h, p_WkT, bk, p_k, N_NODES, DD);
        sgemm128_kernel<<<gemm_grid, 256>>>(h, p_WvT, bv, p_v, N_NODES, DD);
        attn_kernel<<<attn_grid, 256>>>(p_q, p_k, p_v, p_e, p_indptr, p_src, p_phi);
        sgemm128_kernel<<<gemm_grid, 256>>>(h, p_AT, b_anti, p_tmp, N_NODES, DD);
        update_kernel<<<upd_grid, 256>>>(h, p_tmp, p_phi);
    }
}

// round 4
// speedup vs baseline: 1.6296x; 1.6296x over previous
#include <cuda_runtime.h>
#include <math.h>

#define N_NODES 50000
#define N_EDGES 800000
#define DD 128
#define TIME_DIM 32
#define EDGE_DIM 160
#define XDIM 256
#define EPS_F 0.1f
#define GAMMA_F 0.1f

// ---------------- static scratch (allocation-free rule) ----------------
__device__ float g_ea[(size_t)N_EDGES * EDGE_DIM];   // sorted edge_attr [E,160]
__device__ float g_e [(size_t)N_EDGES * DD];         // sorted e = ea@WeT+be [E,128]
__device__ float g_q  [(size_t)N_NODES * DD];
__device__ float g_k  [(size_t)N_NODES * DD];
__device__ float g_v  [(size_t)N_NODES * DD];
__device__ float g_phi[(size_t)N_NODES * DD];
__device__ float g_tmp[(size_t)N_NODES * DD];
__device__ float g_encWT[XDIM * DD];
__device__ float g_WeT[EDGE_DIM * DD];
__device__ float g_WqT[DD * DD];
__device__ float g_WkT[DD * DD];
__device__ float g_WvT[DD * DD];
__device__ float g_AT [DD * DD];
__device__ int   g_cnt[N_NODES];
__device__ int   g_indptr[N_NODES + 1];
__device__ int   g_cursor[N_NODES];
__device__ int   g_perm[N_EDGES];
__device__ int   g_src [N_EDGES];

// ---------------- helpers ----------------
__device__ __forceinline__ float to_tf32(float x) {
    float y;
    asm("cvt.rna.tf32.f32 %0, %1;" : "=f"(y) : "f"(x));
    return y;
}

__device__ __forceinline__ void mma_tf32(float* d, const unsigned* a, const unsigned* b) {
    asm volatile(
        "mma.sync.aligned.m16n8k8.row.col.f32.tf32.tf32.f32 "
        "{%0,%1,%2,%3}, {%4,%5,%6,%7}, {%8,%9}, {%0,%1,%2,%3};"
        : "+f"(d[0]), "+f"(d[1]), "+f"(d[2]), "+f"(d[3])
        : "r"(a[0]), "r"(a[1]), "r"(a[2]), "r"(a[3]), "r"(b[0]), "r"(b[1]));
}

// ---------------- small prep kernels ----------------
__global__ void transpose_kernel(const float* __restrict__ in, float* __restrict__ out,
                                 int R, int C) {
    int i = blockIdx.x * blockDim.x + threadIdx.x;
    if (i < R * C) {
        int r = i / C, c = i % C;
        out[c * R + r] = in[i];
    }
}

// AT[j*D + i] = A[i][j],  A = W - W^T - gamma*I
__global__ void build_AT_kernel(const float* __restrict__ W, float* __restrict__ AT) {
    int i = blockIdx.x * blockDim.x + threadIdx.x;
    if (i < DD * DD) {
        int jj = i / DD, ii = i % DD;
        float val = W[ii * DD + jj] - W[jj * DD + ii] - ((ii == jj) ? GAMMA_F : 0.0f);
        AT[jj * DD + ii] = val;
    }
}

__global__ void zero_int_kernel(int* __restrict__ p, int n) {
    int i = blockIdx.x * blockDim.x + threadIdx.x;
    if (i < n) p[i] = 0;
}

__global__ void count_dst_kernel(const int* __restrict__ ei, int* __restrict__ cnt) {
    int e = blockIdx.x * blockDim.x + threadIdx.x;
    if (e < N_EDGES) atomicAdd(&cnt[ei[N_EDGES + e]], 1);
}

__global__ void scan_kernel(const int* __restrict__ cnt, int* __restrict__ indptr,
                            int* __restrict__ cursor) {
    __shared__ int sm[1024];
    __shared__ int carry;
    if (threadIdx.x == 0) carry = 0;
    __syncthreads();
    for (int base = 0; base < N_NODES; base += 1024) {
        int i = base + threadIdx.x;
        int val = (i < N_NODES) ? cnt[i] : 0;
        sm[threadIdx.x] = val;
        __syncthreads();
        for (int off = 1; off < 1024; off <<= 1) {
            int add = 0;
            if (threadIdx.x >= off) add = sm[threadIdx.x - off];
            __syncthreads();
            sm[threadIdx.x] += add;
            __syncthreads();
        }
        if (i < N_NODES) {
            int excl = carry + sm[threadIdx.x] - val;
            indptr[i] = excl;
            cursor[i] = excl;
        }
        __syncthreads();
        if (threadIdx.x == 0) carry += sm[1023];
        __syncthreads();
    }
    if (threadIdx.x == 0) indptr[N_NODES] = carry;
}

__global__ void scatter_perm_kernel(const int* __restrict__ ei,
                                    int* __restrict__ cursor, int* __restrict__ perm) {
    int e = blockIdx.x * blockDim.x + threadIdx.x;
    if (e < N_EDGES) {
        int d = ei[N_EDGES + e];
        int pos = atomicAdd(&cursor[d], 1);
        perm[pos] = e;
    }
}

// Build sorted edge_attr [E,160] = [msg | cos(rel_t*te_w + te_b)], plus sorted src ids.
__global__ void build_ea_kernel(const int* __restrict__ ei,
                                const float* __restrict__ last_update,
                                const float* __restrict__ t,
                                const float* __restrict__ msg,
                                const float* __restrict__ te_w,
                                const float* __restrict__ te_b,
                                const int* __restrict__ perm,
                                float* __restrict__ ea, int* __restrict__ srcs) {
    int warp = (blockIdx.x * blockDim.x + threadIdx.x) >> 5;
    int lane = threadIdx.x & 31;
    int nwarps = (gridDim.x * blockDim.x) >> 5;
    for (int i = warp; i < N_EDGES; i += nwarps) {
        int eid = perm[i];
        int src = ei[eid];
        float rel = fabsf(last_update[src] - t[eid]);
        if (lane == 0) srcs[i] = src;
        const float* mrow = msg + (size_t)eid * DD;
        float* orow = ea + (size_t)i * EDGE_DIM;
#pragma unroll
        for (int j = 0; j < 4; j++) orow[lane + 32 * j] = mrow[lane + 32 * j];
        orow[lane + 128] = cosf(rel * te_w[lane] + te_b[lane]);
    }
}

// ---------------- tf32 tensor-core GEMM ----------------
// C[M,128] = A[M,K] @ B[K,128] + bias.  K % 32 == 0, K <= 256.
// 128x128 block tile, 256 threads = 8 warps (2 m-groups x 4 n-groups),
// each warp computes 64x32 via 4x4 grid of m16n8k8 tf32 mma tiles.
#define APAD 36   // 32 + 4 floats per A-row in smem (float4-aligned, conflict-free frags)
#define BPAD 132  // 128 + 4 floats per B(k)-row in smem
__global__ void __launch_bounds__(256) tf32gemm_kernel(
    const float* __restrict__ A, const float* __restrict__ B,
    const float* __restrict__ bias, float* __restrict__ C, int M, int K) {
    __shared__ float As[128 * APAD];
    __shared__ float Bs[32 * BPAD];
    int tid = threadIdx.x;
    int lane = tid & 31;
    int warp = tid >> 5;
    int wm = warp >> 2;          // 0..1
    int wn = warp & 3;           // 0..3
    int row0 = blockIdx.x * 128;

    float acc[4][4][4];
#pragma unroll
    for (int i = 0; i < 4; i++)
#pragma unroll
        for (int j = 0; j < 4; j++)
#pragma unroll
            for (int r = 0; r < 4; r++) acc[i][j][r] = 0.0f;

    for (int k0 = 0; k0 < K; k0 += 32) {
        // load A tile: 128 rows x 32 k, as float4, cvt to tf32 on store
#pragma unroll
        for (int j = 0; j < 4; j++) {
            int s = tid + j * 256;          // 0..1023 float4 slots
            int r = s >> 3;                 // 0..127
            int kq = s & 7;                 // float4 slot within 32
            float4 val = make_float4(0.f, 0.f, 0.f, 0.f);
            int gr = row0 + r;
            if (gr < M) val = *(const float4*)(A + (size_t)gr * K + k0 + kq * 4);
            float4 tv = make_float4(to_tf32(val.x), to_tf32(val.y),
                                    to_tf32(val.z), to_tf32(val.w));
            *(float4*)(&As[r * APAD + kq * 4]) = tv;
        }
        // load B tile: 32 k-rows x 128 n
#pragma unroll
        for (int j = 0; j < 4; j++) {
            int s = tid + j * 256;
            int kk = s >> 5;                // 0..31
            int nq = s & 31;                // float4 slot within 128
            float4 val = *(const float4*)(B + (size_t)(k0 + kk) * 128 + nq * 4);
            float4 tv = make_float4(to_tf32(val.x), to_tf32(val.y),
                                    to_tf32(val.z), to_tf32(val.w));
            *(float4*)(&Bs[kk * BPAD + nq * 4]) = tv;
        }
        __syncthreads();
#pragma unroll
        for (int ks = 0; ks < 4; ks++) {
            unsigned a[4][4], b[4][2];
            int kfa = ks * 8 + (lane & 3);
#pragma unroll
            for (int i = 0; i < 4; i++) {
                int r0 = wm * 64 + i * 16 + (lane >> 2);
                a[i][0] = __float_as_uint(As[r0 * APAD + kfa]);
                a[i][1] = __float_as_uint(As[(r0 + 8) * APAD + kfa]);
                a[i][2] = __float_as_uint(As[r0 * APAD + kfa + 4]);
                a[i][3] = __float_as_uint(As[(r0 + 8) * APAD + kfa + 4]);
            }
            int kb = ks * 8 + (lane & 3);
#pragma unroll
            for (int j = 0; j < 4; j++) {
                int nb = wn * 32 + j * 8 + (lane >> 2);
                b[j][0] = __float_as_uint(Bs[kb * BPAD + nb]);
                b[j][1] = __float_as_uint(Bs[(kb + 4) * BPAD + nb]);
            }
#pragma unroll
            for (int i = 0; i < 4; i++)
#pragma unroll
                for (int j = 0; j < 4; j++) mma_tf32(acc[i][j], a[i], b[j]);
        }
        __syncthreads();
    }
    // epilogue
#pragma unroll
    for (int i = 0; i < 4; i++) {
        int r = row0 + wm * 64 + i * 16 + (lane >> 2);
#pragma unroll
        for (int j = 0; j < 4; j++) {
            int c = wn * 32 + j * 8 + 2 * (lane & 3);
            if (r < M) {
                float2 o = make_float2(acc[i][j][0] + bias[c], acc[i][j][1] + bias[c + 1]);
                *(float2*)(C + (size_t)r * 128 + c) = o;
            }
            if (r + 8 < M) {
                float2 o = make_float2(acc[i][j][2] + bias[c], acc[i][j][3] + bias[c + 1]);
                *(float2*)(C + (size_t)(r + 8) * 128 + c) = o;
            }
        }
    }
}

// ---------------- attention: warp-per-dst online softmax ----------------
__global__ void attn_kernel(const float* __restrict__ q, const float* __restrict__ k,
                            const float* __restrict__ v, const float* __restrict__ e,
                            const int* __restrict__ indptr, const int* __restrict__ srcs,
                            float* __restrict__ phi) {
    int node = (blockIdx.x * blockDim.x + threadIdx.x) >> 5;
    int lane = threadIdx.x & 31;
    if (node >= N_NODES) return;
    int beg = indptr[node];
    int end = indptr[node + 1];
    float4 q4 = *(const float4*)(q + (size_t)node * DD + lane * 4);
    float4 acc = make_float4(0.f, 0.f, 0.f, 0.f);
    float m = -3.0e38f, s = 0.0f;
    const float inv_sqrt_d = 0.08838834764831845f;  // 1/sqrt(128)
    for (int i = beg; i < end; i++) {
        int src = srcs[i];
        float4 e4 = *(const float4*)(e + (size_t)i * DD + lane * 4);
        float4 k4 = *(const float4*)(k + (size_t)src * DD + lane * 4);
        float dot = q4.x * (k4.x + e4.x) + q4.y * (k4.y + e4.y)
                  + q4.z * (k4.z + e4.z) + q4.w * (k4.w + e4.w);
#pragma unroll
        for (int off = 16; off; off >>= 1) dot += __shfl_xor_sync(0xffffffffu, dot, off);
        float l = dot * inv_sqrt_d;
        float mn = fmaxf(m, l);
        float scale = __expf(m - mn);
        float w = __expf(l - mn);
        s = s * scale + w;
        float4 v4 = *(const float4*)(v + (size_t)src * DD + lane * 4);
        acc.x = acc.x * scale + (v4.x + e4.x) * w;
        acc.y = acc.y * scale + (v4.y + e4.y) * w;
        acc.z = acc.z * scale + (v4.z + e4.z) * w;
        acc.w = acc.w * scale + (v4.w + e4.w) * w;
        m = mn;
    }
    float invs = (end > beg) ? (1.0f / s) : 0.0f;
    float4 o = make_float4(acc.x * invs, acc.y * invs, acc.z * invs, acc.w * invs);
    *(float4*)(phi + (size_t)node * DD + lane * 4) = o;
}

// h += eps * tanh(tmp + phi)    (tmp already contains h@A^T + b_anti)
__global__ void update_kernel(float* __restrict__ h, const float* __restrict__ tmp,
                              const float* __restrict__ phi) {
    int i = blockIdx.x * blockDim.x + threadIdx.x;
    if (i < N_NODES * DD) h[i] += EPS_F * tanhf(tmp[i] + phi[i]);
}

// ---------------- launch ----------------
extern "C" void kernel_launch(void* const* d_in, const int* in_sizes, int n_in,
                              void* d_out, int out_size) {
    const float* x     = (const float*)d_in[0];
    const float* lastu = (const float*)d_in[1];
    const float* t     = (const float*)d_in[2];
    const float* msg   = (const float*)d_in[3];
    const int*   ei    = (const int*)d_in[4];   // JAX default x64 disabled -> int32
    const float* enc_W = (const float*)d_in[5];
    const float* enc_b = (const float*)d_in[6];
    const float* te_w  = (const float*)d_in[7];
    const float* te_b  = (const float*)d_in[8];
    const float* Wq = (const float*)d_in[9];   const float* bq = (const float*)d_in[10];
    const float* Wk = (const float*)d_in[11];  const float* bk = (const float*)d_in[12];
    const float* Wv = (const float*)d_in[13];  const float* bv = (const float*)d_in[14];
    const float* We = (const float*)d_in[15];  const float* be = (const float*)d_in[16];
    const float* W_anti = (const float*)d_in[17];
    const float* b_anti = (const float*)d_in[18];
    float* h = (float*)d_out;

    float *p_ea, *p_e, *p_q, *p_k, *p_v, *p_phi, *p_tmp;
    float *p_encWT, *p_WeT, *p_WqT, *p_WkT, *p_WvT, *p_AT;
    int *p_cnt, *p_indptr, *p_cursor, *p_perm, *p_src;
    cudaGetSymbolAddress((void**)&p_ea, g_ea);
    cudaGetSymbolAddress((void**)&p_e, g_e);
    cudaGetSymbolAddress((void**)&p_q, g_q);
    cudaGetSymbolAddress((void**)&p_k, g_k);
    cudaGetSymbolAddress((void**)&p_v, g_v);
    cudaGetSymbolAddress((void**)&p_phi, g_phi);
    cudaGetSymbolAddress((void**)&p_tmp, g_tmp);
    cudaGetSymbolAddress((void**)&p_encWT, g_encWT);
    cudaGetSymbolAddress((void**)&p_WeT, g_WeT);
    cudaGetSymbolAddress((void**)&p_WqT, g_WqT);
    cudaGetSymbolAddress((void**)&p_WkT, g_WkT);
    cudaGetSymbolAddress((void**)&p_WvT, g_WvT);
    cudaGetSymbolAddress((void**)&p_AT, g_AT);
    cudaGetSymbolAddress((void**)&p_cnt, g_cnt);
    cudaGetSymbolAddress((void**)&p_indptr, g_indptr);
    cudaGetSymbolAddress((void**)&p_cursor, g_cursor);
    cudaGetSymbolAddress((void**)&p_perm, g_perm);
    cudaGetSymbolAddress((void**)&p_src, g_src);

    // --- weight prep ---
    transpose_kernel<<<(XDIM * DD + 255) / 256, 256>>>(enc_W, p_encWT, DD, XDIM);
    transpose_kernel<<<(EDGE_DIM * DD + 255) / 256, 256>>>(We, p_WeT, DD, EDGE_DIM);
    transpose_kernel<<<(DD * DD + 255) / 256, 256>>>(Wq, p_WqT, DD, DD);
    transpose_kernel<<<(DD * DD + 255) / 256, 256>>>(Wk, p_WkT, DD, DD);
    transpose_kernel<<<(DD * DD + 255) / 256, 256>>>(Wv, p_WvT, DD, DD);
    build_AT_kernel<<<(DD * DD + 255) / 256, 256>>>(W_anti, p_AT);

    // --- CSR by dst ---
    zero_int_kernel<<<(N_NODES + 255) / 256, 256>>>(p_cnt, N_NODES);
    count_dst_kernel<<<(N_EDGES + 255) / 256, 256>>>(ei, p_cnt);
    scan_kernel<<<1, 1024>>>(p_cnt, p_indptr, p_cursor);
    scatter_perm_kernel<<<(N_EDGES + 255) / 256, 256>>>(ei, p_cursor, p_perm);

    // --- sorted edge_attr + e GEMM ---
    build_ea_kernel<<<800, 256>>>(ei, lastu, t, msg, te_w, te_b, p_perm, p_ea, p_src);
    tf32gemm_kernel<<<(N_EDGES + 127) / 128, 256>>>(p_ea, p_WeT, be, p_e, N_EDGES, EDGE_DIM);

    // --- h = x @ enc_W^T + enc_b ---
    tf32gemm_kernel<<<(N_NODES + 127) / 128, 256>>>(x, p_encWT, enc_b, h, N_NODES, XDIM);

    // --- 3 iterations ---
    int gemm_grid = (N_NODES + 127) / 128;
    int attn_grid = (N_NODES * 32 + 255) / 256;
    int upd_grid = (N_NODES * DD + 255) / 256;
    for (int it = 0; it < 3; it++) {
        tf32gemm_kernel<<<gemm_grid, 256>>>(h, p_WqT, bq, p_q, N_NODES, DD);
        tf32gemm_kernel<<<gemm_grid, 256>>>(h, p_WkT, bk, p_k, N_NODES, DD);
        tf32gemm_kernel<<<gemm_grid, 256>>>(h, p_WvT, bv, p_v, N_NODES, DD);
        attn_kernel<<<attn_grid, 256>>>(p_q, p_k, p_v, p_e, p_indptr, p_src, p_phi);
        tf32gemm_kernel<<<gemm_grid, 256>>>(h, p_AT, b_anti, p_tmp, N_NODES, DD);
        update_kernel<<<upd_grid, 256>>>(h, p_tmp, p_phi);
    }
}

// round 8
// speedup vs baseline: 1.7263x; 1.0593x over previous
#include <cuda_runtime.h>
#include <math.h>

#define N_NODES 50000
#define N_EDGES 800000
#define DD 128
#define TIME_DIM 32
#define EDGE_DIM 160
#define XDIM 256
#define EPS_F 0.1f
#define GAMMA_F 0.1f

// ---------------- static scratch (allocation-free rule) ----------------
__device__ float g_e [(size_t)N_EDGES * DD];         // sorted e = ea@WeT+be [E,128]
__device__ float g_q  [(size_t)N_NODES * DD];
__device__ float g_k  [(size_t)N_NODES * DD];
__device__ float g_v  [(size_t)N_NODES * DD];
__device__ float g_tmp[(size_t)N_NODES * DD];
__device__ float g_encWT[XDIM * DD];
__device__ float g_WeT[EDGE_DIM * DD];
__device__ float g_B4[4 * DD * DD];     // [WqT | WkT | WvT | AT], each [128k x 128n]
__device__ float g_bias4[4 * DD];
__device__ int   g_cnt[N_NODES];
__device__ int   g_indptr[N_NODES + 1];
__device__ int   g_cursor[N_NODES];
__device__ int   g_perm[N_EDGES];
__device__ int   g_src [N_EDGES];
__device__ float g_rel [N_EDGES];

// ---------------- helpers ----------------
__device__ __forceinline__ float to_tf32(float x) {
    float y;
    asm("cvt.rna.tf32.f32 %0, %1;" : "=f"(y) : "f"(x));
    return y;
}

__device__ __forceinline__ void mma_tf32(float* d, const unsigned* a, const unsigned* b) {
    asm volatile(
        "mma.sync.aligned.m16n8k8.row.col.f32.tf32.tf32.f32 "
        "{%0,%1,%2,%3}, {%4,%5,%6,%7}, {%8,%9}, {%0,%1,%2,%3};"
        : "+f"(d[0]), "+f"(d[1]), "+f"(d[2]), "+f"(d[3])
        : "r"(a[0]), "r"(a[1]), "r"(a[2]), "r"(a[3]), "r"(b[0]), "r"(b[1]));
}

// ---------------- prep kernels ----------------
__global__ void transpose_kernel(const float* __restrict__ in, float* __restrict__ out,
                                 int R, int C) {
    int i = blockIdx.x * blockDim.x + threadIdx.x;
    if (i < R * C) {
        int r = i / C, c = i % C;
        out[c * R + r] = in[i];
    }
}

// Build combined B4 = [WqT | WkT | WvT | AT] and bias4 = [bq|bk|bv|b_anti].
// B[seg][k*128 + n]: segs 0..2 = W[n*128 + k]; seg 3 = A^T[k,n] = A[n,k].
__global__ void build_B4_kernel(const float* __restrict__ Wq, const float* __restrict__ Wk,
                                const float* __restrict__ Wv, const float* __restrict__ Wa,
                                const float* __restrict__ bq, const float* __restrict__ bk,
                                const float* __restrict__ bv, const float* __restrict__ ba,
                                float* __restrict__ B4, float* __restrict__ bias4) {
    int i = blockIdx.x * blockDim.x + threadIdx.x;
    if (i < 4 * DD * DD) {
        int seg = i >> 14;           // /16384
        int rem = i & 16383;
        int kk = rem >> 7;           // k row
        int n  = rem & 127;          // col
        float val;
        if (seg == 0)      val = Wq[n * DD + kk];
        else if (seg == 1) val = Wk[n * DD + kk];
        else if (seg == 2) val = Wv[n * DD + kk];
        else               val = Wa[n * DD + kk] - Wa[kk * DD + n] - ((n == kk) ? GAMMA_F : 0.0f);
        B4[i] = val;
    }
    if (i < 4 * DD) {
        int seg = i >> 7, c = i & 127;
        float b;
        if (seg == 0)      b = bq[c];
        else if (seg == 1) b = bk[c];
        else if (seg == 2) b = bv[c];
        else               b = ba[c];
        bias4[i] = b;
    }
}

__global__ void zero_int_kernel(int* __restrict__ p, int n) {
    int i = blockIdx.x * blockDim.x + threadIdx.x;
    if (i < n) p[i] = 0;
}

__global__ void count_dst_kernel(const int* __restrict__ ei, int* __restrict__ cnt) {
    int e = blockIdx.x * blockDim.x + threadIdx.x;
    if (e < N_EDGES) atomicAdd(&cnt[ei[N_EDGES + e]], 1);
}

__global__ void scan_kernel(const int* __restrict__ cnt, int* __restrict__ indptr,
                            int* __restrict__ cursor) {
    __shared__ int sm[1024];
    __shared__ int carry;
    if (threadIdx.x == 0) carry = 0;
    __syncthreads();
    for (int base = 0; base < N_NODES; base += 1024) {
        int i = base + threadIdx.x;
        int val = (i < N_NODES) ? cnt[i] : 0;
        sm[threadIdx.x] = val;
        __syncthreads();
        for (int off = 1; off < 1024; off <<= 1) {
            int add = 0;
            if (threadIdx.x >= off) add = sm[threadIdx.x - off];
            __syncthreads();
            sm[threadIdx.x] += add;
            __syncthreads();
        }
        if (i < N_NODES) {
            int excl = carry + sm[threadIdx.x] - val;
            indptr[i] = excl;
            cursor[i] = excl;
        }
        __syncthreads();
        if (threadIdx.x == 0) carry += sm[1023];
        __syncthreads();
    }
    if (threadIdx.x == 0) indptr[N_NODES] = carry;
}

// scatter: perm + src + rel in one pass
__global__ void scatter_perm_kernel(const int* __restrict__ ei,
                                    const float* __restrict__ last_update,
                                    const float* __restrict__ t,
                                    int* __restrict__ cursor, int* __restrict__ perm,
                                    int* __restrict__ srcs, float* __restrict__ rel) {
    int e = blockIdx.x * blockDim.x + threadIdx.x;
    if (e < N_EDGES) {
        int d = ei[N_EDGES + e];
        int s = ei[e];
        int pos = atomicAdd(&cursor[d], 1);
        perm[pos] = e;
        srcs[pos] = s;
        rel[pos] = fabsf(last_update[s] - t[e]);
    }
}

// ---------------- tf32 GEMM cores ----------------
#define APAD 36   // 32 + 4 floats per A-row in smem
#define BPAD 132  // 128 + 4 floats per B(k)-row in smem

// Generic: C[M,128] = A[M,K] @ B[K,128] + bias. K % 32 == 0. (used for enc, K=256)
__global__ void __launch_bounds__(256) tf32gemm_kernel(
    const float* __restrict__ A, const float* __restrict__ B,
    const float* __restrict__ bias, float* __restrict__ C, int M, int K) {
    __shared__ float As[128 * APAD];
    __shared__ float Bs[32 * BPAD];
    int tid = threadIdx.x;
    int lane = tid & 31;
    int warp = tid >> 5;
    int wm = warp >> 2;
    int wn = warp & 3;
    int row0 = blockIdx.x * 128;

    float acc[4][4][4];
#pragma unroll
    for (int i = 0; i < 4; i++)
#pragma unroll
        for (int j = 0; j < 4; j++)
#pragma unroll
            for (int r = 0; r < 4; r++) acc[i][j][r] = 0.0f;

    for (int k0 = 0; k0 < K; k0 += 32) {
#pragma unroll
        for (int j = 0; j < 4; j++) {
            int s = tid + j * 256;
            int r = s >> 3;
            int kq = s & 7;
            float4 val = make_float4(0.f, 0.f, 0.f, 0.f);
            int gr = row0 + r;
            if (gr < M) val = *(const float4*)(A + (size_t)gr * K + k0 + kq * 4);
            float4 tv = make_float4(to_tf32(val.x), to_tf32(val.y),
                                    to_tf32(val.z), to_tf32(val.w));
            *(float4*)(&As[r * APAD + kq * 4]) = tv;
        }
#pragma unroll
        for (int j = 0; j < 4; j++) {
            int s = tid + j * 256;
            int kk = s >> 5;
            int nq = s & 31;
            float4 val = *(const float4*)(B + (size_t)(k0 + kk) * 128 + nq * 4);
            float4 tv = make_float4(to_tf32(val.x), to_tf32(val.y),
                                    to_tf32(val.z), to_tf32(val.w));
            *(float4*)(&Bs[kk * BPAD + nq * 4]) = tv;
        }
        __syncthreads();
#pragma unroll
        for (int ks = 0; ks < 4; ks++) {
            unsigned a[4][4], b[4][2];
            int kfa = ks * 8 + (lane & 3);
#pragma unroll
            for (int i = 0; i < 4; i++) {
                int r0 = wm * 64 + i * 16 + (lane >> 2);
                a[i][0] = __float_as_uint(As[r0 * APAD + kfa]);
                a[i][1] = __float_as_uint(As[(r0 + 8) * APAD + kfa]);
                a[i][2] = __float_as_uint(As[r0 * APAD + kfa + 4]);
                a[i][3] = __float_as_uint(As[(r0 + 8) * APAD + kfa + 4]);
            }
#pragma unroll
            for (int j = 0; j < 4; j++) {
                int nb = wn * 32 + j * 8 + (lane >> 2);
                b[j][0] = __float_as_uint(Bs[kfa * BPAD + nb]);
                b[j][1] = __float_as_uint(Bs[(kfa + 4) * BPAD + nb]);
            }
#pragma unroll
            for (int i = 0; i < 4; i++)
#pragma unroll
                for (int j = 0; j < 4; j++) mma_tf32(acc[i][j], a[i], b[j]);
        }
        __syncthreads();
    }
#pragma unroll
    for (int i = 0; i < 4; i++) {
        int r = row0 + wm * 64 + i * 16 + (lane >> 2);
#pragma unroll
        for (int j = 0; j < 4; j++) {
            int c = wn * 32 + j * 8 + 2 * (lane & 3);
            if (r < M) {
                float2 o = make_float2(acc[i][j][0] + bias[c], acc[i][j][1] + bias[c + 1]);
                *(float2*)(C + (size_t)r * 128 + c) = o;
            }
            if (r + 8 < M) {
                float2 o = make_float2(acc[i][j][2] + bias[c], acc[i][j][3] + bias[c + 1]);
                *(float2*)(C + (size_t)(r + 8) * 128 + c) = o;
            }
        }
    }
}

// Multi-output GEMM: K=128 fixed; blockIdx.y selects B-segment/bias-segment/output.
// Computes q,k,v,tmp from h in ONE launch.
__global__ void __launch_bounds__(256) tf32gemm_multi_kernel(
    const float* __restrict__ A, const float* __restrict__ B4,
    const float* __restrict__ bias4,
    float* __restrict__ c0, float* __restrict__ c1,
    float* __restrict__ c2, float* __restrict__ c3, int M) {
    __shared__ float As[128 * APAD];
    __shared__ float Bs[32 * BPAD];
    int tid = threadIdx.x;
    int lane = tid & 31;
    int warp = tid >> 5;
    int wm = warp >> 2;
    int wn = warp & 3;
    int row0 = blockIdx.x * 128;
    int seg = blockIdx.y;
    const float* B = B4 + seg * DD * DD;
    const float* bias = bias4 + seg * DD;
    float* C = (seg == 0) ? c0 : (seg == 1) ? c1 : (seg == 2) ? c2 : c3;

    float acc[4][4][4];
#pragma unroll
    for (int i = 0; i < 4; i++)
#pragma unroll
        for (int j = 0; j < 4; j++)
#pragma unroll
            for (int r = 0; r < 4; r++) acc[i][j][r] = 0.0f;

    for (int k0 = 0; k0 < DD; k0 += 32) {
#pragma unroll
        for (int j = 0; j < 4; j++) {
            int s = tid + j * 256;
            int r = s >> 3;
            int kq = s & 7;
            float4 val = make_float4(0.f, 0.f, 0.f, 0.f);
            int gr = row0 + r;
            if (gr < M) val = *(const float4*)(A + (size_t)gr * DD + k0 + kq * 4);
            float4 tv = make_float4(to_tf32(val.x), to_tf32(val.y),
                                    to_tf32(val.z), to_tf32(val.w));
            *(float4*)(&As[r * APAD + kq * 4]) = tv;
        }
#pragma unroll
        for (int j = 0; j < 4; j++) {
            int s = tid + j * 256;
            int kk = s >> 5;
            int nq = s & 31;
            float4 val = *(const float4*)(B + (size_t)(k0 + kk) * 128 + nq * 4);
            float4 tv = make_float4(to_tf32(val.x), to_tf32(val.y),
                                    to_tf32(val.z), to_tf32(val.w));
            *(float4*)(&Bs[kk * BPAD + nq * 4]) = tv;
        }
        __syncthreads();
#pragma unroll
        for (int ks = 0; ks < 4; ks++) {
            unsigned a[4][4], b[4][2];
            int kfa = ks * 8 + (lane & 3);
#pragma unroll
            for (int i = 0; i < 4; i++) {
                int r0 = wm * 64 + i * 16 + (lane >> 2);
                a[i][0] = __float_as_uint(As[r0 * APAD + kfa]);
                a[i][1] = __float_as_uint(As[(r0 + 8) * APAD + kfa]);
                a[i][2] = __float_as_uint(As[r0 * APAD + kfa + 4]);
                a[i][3] = __float_as_uint(As[(r0 + 8) * APAD + kfa + 4]);
            }
#pragma unroll
            for (int j = 0; j < 4; j++) {
                int nb = wn * 32 + j * 8 + (lane >> 2);
                b[j][0] = __float_as_uint(Bs[kfa * BPAD + nb]);
                b[j][1] = __float_as_uint(Bs[(kfa + 4) * BPAD + nb]);
            }
#pragma unroll
            for (int i = 0; i < 4; i++)
#pragma unroll
                for (int j = 0; j < 4; j++) mma_tf32(acc[i][j], a[i], b[j]);
        }
        __syncthreads();
    }
#pragma unroll
    for (int i = 0; i < 4; i++) {
        int r = row0 + wm * 64 + i * 16 + (lane >> 2);
#pragma unroll
        for (int j = 0; j < 4; j++) {
            int c = wn * 32 + j * 8 + 2 * (lane & 3);
            if (r < M) {
                float2 o = make_float2(acc[i][j][0] + bias[c], acc[i][j][1] + bias[c + 1]);
                *(float2*)(C + (size_t)r * 128 + c) = o;
            }
            if (r + 8 < M) {
                float2 o = make_float2(acc[i][j][2] + bias[c], acc[i][j][3] + bias[c + 1]);
                *(float2*)(C + (size_t)(r + 8) * 128 + c) = o;
            }
        }
    }
}

// Fused edge GEMM: e[i,:] = [msg[perm[i]] | cos(rel[i]*te_w + te_b)] @ WeT + be
// K = 160 (5 chunks of 32): chunks 0-3 gather msg, chunk 4 computes time encoding.
// N_EDGES % 128 == 0 -> no row bounds checks.
__global__ void __launch_bounds__(256) edge_gemm_kernel(
    const float* __restrict__ msg, const int* __restrict__ perm,
    const float* __restrict__ rel, const float* __restrict__ WeT,
    const float* __restrict__ te_w, const float* __restrict__ te_b,
    const float* __restrict__ be, float* __restrict__ e) {
    __shared__ float As[128 * APAD];
    __shared__ float Bs[32 * BPAD];
    __shared__ float rel_s[128];
    __shared__ int   eid_s[128];
    __shared__ float tw_s[32], tb_s[32];
    int tid = threadIdx.x;
    int lane = tid & 31;
    int warp = tid >> 5;
    int wm = warp >> 2;
    int wn = warp & 3;
    int row0 = blockIdx.x * 128;

    if (tid < 128) {
        eid_s[tid] = perm[row0 + tid];
        rel_s[tid] = rel[row0 + tid];
    } else if (tid < 160) {
        tw_s[tid - 128] = te_w[tid - 128];
        tb_s[tid - 128] = te_b[tid - 128];
    }
    __syncthreads();

    float acc[4][4][4];
#pragma unroll
    for (int i = 0; i < 4; i++)
#pragma unroll
        for (int j = 0; j < 4; j++)
#pragma unroll
            for (int r = 0; r < 4; r++) acc[i][j][r] = 0.0f;

    for (int chunk = 0; chunk < 5; chunk++) {
        if (chunk < 4) {
#pragma unroll
            for (int j = 0; j < 4; j++) {
                int s = tid + j * 256;
                int r = s >> 3;
                int kq = s & 7;
                float4 val = *(const float4*)(msg + (size_t)eid_s[r] * DD + chunk * 32 + kq * 4);
                float4 tv = make_float4(to_tf32(val.x), to_tf32(val.y),
                                        to_tf32(val.z), to_tf32(val.w));
                *(float4*)(&As[r * APAD + kq * 4]) = tv;
            }
        } else {
#pragma unroll
            for (int j = 0; j < 4; j++) {
                int s = tid + j * 256;
                int r = s >> 3;
                int kq = s & 7;
                float rv = rel_s[r];
                float4 tv;
                tv.x = to_tf32(cosf(rv * tw_s[kq * 4 + 0] + tb_s[kq * 4 + 0]));
                tv.y = to_tf32(cosf(rv * tw_s[kq * 4 + 1] + tb_s[kq * 4 + 1]));
                tv.z = to_tf32(cosf(rv * tw_s[kq * 4 + 2] + tb_s[kq * 4 + 2]));
                tv.w = to_tf32(cosf(rv * tw_s[kq * 4 + 3] + tb_s[kq * 4 + 3]));
                *(float4*)(&As[r * APAD + kq * 4]) = tv;
            }
        }
#pragma unroll
        for (int j = 0; j < 4; j++) {
            int s = tid + j * 256;
            int kk = s >> 5;
            int nq = s & 31;
            float4 val = *(const float4*)(WeT + (size_t)(chunk * 32 + kk) * 128 + nq * 4);
            float4 tv = make_float4(to_tf32(val.x), to_tf32(val.y),
                                    to_tf32(val.z), to_tf32(val.w));
            *(float4*)(&Bs[kk * BPAD + nq * 4]) = tv;
        }
        __syncthreads();
#pragma unroll
        for (int ks = 0; ks < 4; ks++) {
            unsigned a[4][4], b[4][2];
            int kfa = ks * 8 + (lane & 3);
#pragma unroll
            for (int i = 0; i < 4; i++) {
                int r0 = wm * 64 + i * 16 + (lane >> 2);
                a[i][0] = __float_as_uint(As[r0 * APAD + kfa]);
                a[i][1] = __float_as_uint(As[(r0 + 8) * APAD + kfa]);
                a[i][2] = __float_as_uint(As[r0 * APAD + kfa + 4]);
                a[i][3] = __float_as_uint(As[(r0 + 8) * APAD + kfa + 4]);
            }
#pragma unroll
            for (int j = 0; j < 4; j++) {
                int nb = wn * 32 + j * 8 + (lane >> 2);
                b[j][0] = __float_as_uint(Bs[kfa * BPAD + nb]);
                b[j][1] = __float_as_uint(Bs[(kfa + 4) * BPAD + nb]);
            }
#pragma unroll
            for (int i = 0; i < 4; i++)
#pragma unroll
                for (int j = 0; j < 4; j++) mma_tf32(acc[i][j], a[i], b[j]);
        }
        __syncthreads();
    }
#pragma unroll
    for (int i = 0; i < 4; i++) {
        int r = row0 + wm * 64 + i * 16 + (lane >> 2);
#pragma unroll
        for (int j = 0; j < 4; j++) {
            int c = wn * 32 + j * 8 + 2 * (lane & 3);
            float2 o0 = make_float2(acc[i][j][0] + be[c], acc[i][j][1] + be[c + 1]);
            *(float2*)(e + (size_t)r * 128 + c) = o0;
            float2 o1 = make_float2(acc[i][j][2] + be[c], acc[i][j][3] + be[c + 1]);
            *(float2*)(e + (size_t)(r + 8) * 128 + c) = o1;
        }
    }
}

// ---------------- attention + fused update: warp-per-dst online softmax ----------------
// h[node] += eps * tanh(tmp[node] + phi[node])
__global__ void attn_update_kernel(const float* __restrict__ q, const float* __restrict__ k,
                                   const float* __restrict__ v, const float* __restrict__ e,
                                   const int* __restrict__ indptr, const int* __restrict__ srcs,
                                   const float* __restrict__ tmp, float* __restrict__ h) {
    int node = (blockIdx.x * blockDim.x + threadIdx.x) >> 5;
    int lane = threadIdx.x & 31;
    if (node >= N_NODES) return;
    int beg = indptr[node];
    int end = indptr[node + 1];
    float4 q4 = *(const float4*)(q + (size_t)node * DD + lane * 4);
    float4 acc = make_float4(0.f, 0.f, 0.f, 0.f);
    float m = -3.0e38f, s = 0.0f;
    const float inv_sqrt_d = 0.08838834764831845f;  // 1/sqrt(128)
    for (int i = beg; i < end; i++) {
        int src = srcs[i];
        float4 e4 = *(const float4*)(e + (size_t)i * DD + lane * 4);
        float4 k4 = *(const float4*)(k + (size_t)src * DD + lane * 4);
        float dot = q4.x * (k4.x + e4.x) + q4.y * (k4.y + e4.y)
                  + q4.z * (k4.z + e4.z) + q4.w * (k4.w + e4.w);
#pragma unroll
        for (int off = 16; off; off >>= 1) dot += __shfl_xor_sync(0xffffffffu, dot, off);
        float l = dot * inv_sqrt_d;
        float mn = fmaxf(m, l);
        float scale = __expf(m - mn);
        float w = __expf(l - mn);
        s = s * scale + w;
        float4 v4 = *(const float4*)(v + (size_t)src * DD + lane * 4);
        acc.x = acc.x * scale + (v4.x + e4.x) * w;
        acc.y = acc.y * scale + (v4.y + e4.y) * w;
        acc.z = acc.z * scale + (v4.z + e4.z) * w;
        acc.w = acc.w * scale + (v4.w + e4.w) * w;
        m = mn;
    }
    float invs = (end > beg) ? (1.0f / s) : 0.0f;
    float4 t4 = *(const float4*)(tmp + (size_t)node * DD + lane * 4);
    float4 h4 = *(const float4*)(h + (size_t)node * DD + lane * 4);
    h4.x += EPS_F * tanhf(t4.x + acc.x * invs);
    h4.y += EPS_F * tanhf(t4.y + acc.y * invs);
    h4.z += EPS_F * tanhf(t4.z + acc.z * invs);
    h4.w += EPS_F * tanhf(t4.w + acc.w * invs);
    *(float4*)(h + (size_t)node * DD + lane * 4) = h4;
}

// ---------------- launch ----------------
extern "C" void kernel_launch(void* const* d_in, const int* in_sizes, int n_in,
                              void* d_out, int out_size) {
    const float* x     = (const float*)d_in[0];
    const float* lastu = (const float*)d_in[1];
    const float* t     = (const float*)d_in[2];
    const float* msg   = (const float*)d_in[3];
    const int*   ei    = (const int*)d_in[4];   // JAX default x64 disabled -> int32
    const float* enc_W = (const float*)d_in[5];
    const float* enc_b = (const float*)d_in[6];
    const float* te_w  = (const float*)d_in[7];
    const float* te_b  = (const float*)d_in[8];
    const float* Wq = (const float*)d_in[9];   const float* bq = (const float*)d_in[10];
    const float* Wk = (const float*)d_in[11];  const float* bk = (const float*)d_in[12];
    const float* Wv = (const float*)d_in[13];  const float* bv = (const float*)d_in[14];
    const float* We = (const float*)d_in[15];  const float* be = (const float*)d_in[16];
    const float* W_anti = (const float*)d_in[17];
    const float* b_anti = (const float*)d_in[18];
    float* h = (float*)d_out;

    float *p_e, *p_q, *p_k, *p_v, *p_tmp;
    float *p_encWT, *p_WeT, *p_B4, *p_bias4, *p_rel;
    int *p_cnt, *p_indptr, *p_cursor, *p_perm, *p_src;
    cudaGetSymbolAddress((void**)&p_e, g_e);
    cudaGetSymbolAddress((void**)&p_q, g_q);
    cudaGetSymbolAddress((void**)&p_k, g_k);
    cudaGetSymbolAddress((void**)&p_v, g_v);
    cudaGetSymbolAddress((void**)&p_tmp, g_tmp);
    cudaGetSymbolAddress((void**)&p_encWT, g_encWT);
    cudaGetSymbolAddress((void**)&p_WeT, g_WeT);
    cudaGetSymbolAddress((void**)&p_B4, g_B4);
    cudaGetSymbolAddress((void**)&p_bias4, g_bias4);
    cudaGetSymbolAddress((void**)&p_rel, g_rel);
    cudaGetSymbolAddress((void**)&p_cnt, g_cnt);
    cudaGetSymbolAddress((void**)&p_indptr, g_indptr);
    cudaGetSymbolAddress((void**)&p_cursor, g_cursor);
    cudaGetSymbolAddress((void**)&p_perm, g_perm);
    cudaGetSymbolAddress((void**)&p_src, g_src);

    // --- weight prep ---
    transpose_kernel<<<(XDIM * DD + 255) / 256, 256>>>(enc_W, p_encWT, DD, XDIM);
    transpose_kernel<<<(EDGE_DIM * DD + 255) / 256, 256>>>(We, p_WeT, DD, EDGE_DIM);
    build_B4_kernel<<<(4 * DD * DD + 255) / 256, 256>>>(Wq, Wk, Wv, W_anti,
                                                        bq, bk, bv, b_anti, p_B4, p_bias4);

    // --- CSR by dst (includes src + rel precompute) ---
    zero_int_kernel<<<(N_NODES + 255) / 256, 256>>>(p_cnt, N_NODES);
    count_dst_kernel<<<(N_EDGES + 255) / 256, 256>>>(ei, p_cnt);
    scan_kernel<<<1, 1024>>>(p_cnt, p_indptr, p_cursor);
    scatter_perm_kernel<<<(N_EDGES + 255) / 256, 256>>>(ei, lastu, t, p_cursor,
                                                        p_perm, p_src, p_rel);

    // --- fused edge-feature GEMM: e = [msg|timeenc] @ WeT + be ---
    edge_gemm_kernel<<<N_EDGES / 128, 256>>>(msg, p_perm, p_rel, p_WeT, te_w, te_b, be, p_e);

    // --- h = x @ enc_W^T + enc_b ---
    tf32gemm_kernel<<<(N_NODES + 127) / 128, 256>>>(x, p_encWT, enc_b, h, N_NODES, XDIM);

    // --- 3 iterations ---
    dim3 multi_grid((N_NODES + 127) / 128, 4);
    int attn_grid = (N_NODES * 32 + 255) / 256;
    for (int it = 0; it < 3; it++) {
        tf32gemm_multi_kernel<<<multi_grid, 256>>>(h, p_B4, p_bias4,
                                                   p_q, p_k, p_v, p_tmp, N_NODES);
        attn_update_kernel<<<attn_grid, 256>>>(p_q, p_k, p_v, p_e,
                                               p_indptr, p_src, p_tmp, h);
    }
}